// round 1
// baseline (speedup 1.0000x reference)
#include <cuda_runtime.h>

// Problem constants
#define Bv   16
#define Cv   2
#define Tv   2000
#define Fv   257
#define NCH  25          // number of time chunks
#define Lc   80          // chunk length (NCH*Lc == Tv)
#define BF   (Bv*Fv)     // 4112 independent scan chains

// Scratch (no cudaMalloc allowed): chunk-end partials and carry-ins.
__device__ float g_e[NCH * BF];
__device__ float g_carry[NCH * BF];

__device__ __forceinline__ float sigmoidf(float x) {
    return 1.0f / (1.0f + expf(-x));
}

// K1: chunk-local EMA scan (zero initial state), record chunk-end value only.
// Thread id -> (b, chunk, f) with f fastest for coalescing.
__global__ void k1_partial(const float* __restrict__ in,
                           const float* __restrict__ alpha_p) {
    int id = blockIdx.x * blockDim.x + threadIdx.x;
    if (id >= Bv * NCH * Fv) return;
    int f  = id % Fv;
    int bc = id / Fv;
    int ch = bc % NCH;
    int b  = bc / NCH;

    float alpha = sigmoidf(alpha_p[f]);
    float s = 0.0f;
    const float2* x = (const float2*)in + ((size_t)(b * Cv + 0) * Tv + (size_t)ch * Lc) * Fv + f;
#pragma unroll 8
    for (int t = 0; t < Lc; ++t) {
        float2 v = x[(size_t)t * Fv];
        float m = fmaf(v.x, v.x, v.y * v.y);
        s = fmaf(alpha, m - s, s);          // s = s*(1-a) + m*a
    }
    g_e[ch * BF + b * Fv + f] = s;
}

// K2: sequential combine over 25 chunks per chain: carry_in[k] = state before chunk k.
__global__ void k2_combine(const float* __restrict__ s1,
                           const float* __restrict__ alpha_p) {
    int id = blockIdx.x * blockDim.x + threadIdx.x;  // id = b*Fv + f
    if (id >= BF) return;
    int f = id % Fv;
    float alpha = sigmoidf(alpha_p[f]);
    float aL = powf(1.0f - alpha, (float)Lc);
    float s = s1[id];                                // s_1[b,0,f,0]
#pragma unroll
    for (int k = 0; k < NCH; ++k) {
        g_carry[k * BF + id] = s;
        s = fmaf(aL, s, g_e[k * BF + id]);           // state after chunk k
    }
}

// K3: re-scan each chunk with correct carry-in; emit smooth (sqrt) + res channel 0.
__global__ void k3_final(const float* __restrict__ in,
                         const float* __restrict__ alpha_p,
                         const float* __restrict__ w,
                         const float* __restrict__ bi,
                         float* __restrict__ res,
                         float* __restrict__ sfin,
                         float* __restrict__ smooth) {
    int id = blockIdx.x * blockDim.x + threadIdx.x;
    if (id >= Bv * NCH * Fv) return;
    int f  = id % Fv;
    int bc = id / Fv;
    int ch = bc % NCH;
    int b  = bc / NCH;

    float alpha = sigmoidf(alpha_p[f]);
    float w0 = w[f];        // weights[0, c=0, 0, f, 0]
    float b0 = bi[f];
    float s = g_carry[ch * BF + b * Fv + f];

    size_t base = ((size_t)(b * Cv + 0) * Tv + (size_t)ch * Lc) * Fv + f;
    const float2* x = (const float2*)in + base;
    float2* r = (float2*)res + base;
    float* sm = smooth ? smooth + ((size_t)b * Tv + (size_t)ch * Lc) * Fv + f : (float*)0;

#pragma unroll 4
    for (int t = 0; t < Lc; ++t) {
        float2 v = x[(size_t)t * Fv];
        float m = fmaf(v.x, v.x, v.y * v.y);
        s = fmaf(alpha, m - s, s);
        float sd = sqrtf(s);
        float inv = w0 / (sd + 1e-8f);
        float2 o;
        o.x = fmaf(v.x, inv, b0);
        o.y = fmaf(v.y, inv, b0);
        r[(size_t)t * Fv] = o;
        if (sm) sm[(size_t)t * Fv] = sd;
    }
    if (ch == NCH - 1 && sfin) sfin[b * Fv + f] = s;   // s_final == last smooth state
}

// K4: channel-1 elementwise: res = x / (sqrt(|x|^2)+1e-8) * w1 + b1
__global__ void k4_ch1(const float* __restrict__ in,
                       const float* __restrict__ w,
                       const float* __restrict__ bi,
                       float* __restrict__ res) {
    int idx = blockIdx.x * blockDim.x + threadIdx.x;   // over B*T*F
    if (idx >= Bv * Tv * Fv) return;
    int f  = idx % Fv;
    int bt = idx / Fv;
    int t  = bt % Tv;
    int b  = bt / Tv;

    size_t off = ((size_t)(b * Cv + 1) * Tv + t) * Fv + f;
    float2 v = ((const float2*)in)[off];
    float mag = sqrtf(fmaf(v.x, v.x, v.y * v.y));
    float w1 = w[Fv + f];
    float b1 = bi[Fv + f];
    float inv = w1 / (mag + 1e-8f);
    float2 o;
    o.x = fmaf(v.x, inv, b1);
    o.y = fmaf(v.y, inv, b1);
    ((float2*)res)[off] = o;
}

extern "C" void kernel_launch(void* const* d_in, const int* in_sizes, int n_in,
                              void* d_out, int out_size) {
    const float* in  = (const float*)d_in[0];   // [B,C,T,F,2]
    const float* s1  = (const float*)d_in[1];   // [B,1,F,1]
    const float* w   = (const float*)d_in[2];   // [1,C,1,F,1]
    const float* bi  = (const float*)d_in[3];   // [1,C,1,F,1]
    const float* ap  = (const float*)d_in[4];   // [1,1,F,1]

    float* out = (float*)d_out;
    const long long RESN = (long long)Bv * Cv * Tv * Fv * 2;  // 32,896,000
    const long long SFN  = (long long)BF;                     // 4,112
    const long long SMN  = (long long)Bv * Tv * Fv;           // 8,224,000

    float* res    = out;
    float* sfin   = (float*)0;
    float* smooth = (float*)0;
    long long osz = (long long)out_size;
    if (osz >= RESN + SFN + SMN) {            // (res, s_final, smooth_data) concatenated
        sfin   = out + RESN;
        smooth = out + RESN + SFN;
    } else if (osz >= RESN + SMN) {           // (res, smooth_data)
        smooth = out + RESN;
    }

    const int BLK = 256;
    int n1 = Bv * NCH * Fv;                   // 102,800
    k1_partial<<<(n1 + BLK - 1) / BLK, BLK>>>(in, ap);
    k2_combine<<<(BF + BLK - 1) / BLK, BLK>>>(s1, ap);
    k3_final  <<<(n1 + BLK - 1) / BLK, BLK>>>(in, ap, w, bi, res, sfin, smooth);
    int n4 = Bv * Tv * Fv;                    // 8,224,000
    k4_ch1    <<<(n4 + BLK - 1) / BLK, BLK>>>(in, w, bi, res);
}

// round 2
// speedup vs baseline: 1.1261x; 1.1261x over previous
#include <cuda_runtime.h>

// Problem constants
#define Bv   16
#define Cv   2
#define Tv   2000
#define Fv   257
#define NCH  40          // number of time chunks
#define Lc   50          // chunk length (NCH*Lc == Tv)
#define BF   (Bv*Fv)     // 4112 independent scan chains

// Scratch (no cudaMalloc allowed): chunk-end partials and carry-ins.
__device__ float g_e[NCH * BF];
__device__ float g_carry[NCH * BF];

__device__ __forceinline__ float sigmoidf(float x) {
    return 1.0f / (1.0f + expf(-x));
}

// K1 (fused): chunk-local EMA partial scan on channel 0 (zero init state,
// record chunk-end value), PLUS the independent channel-1 elementwise
// normalization for the same (b, t, f) range.
// Thread id -> (b, chunk, f) with f fastest for coalescing.
__global__ void __launch_bounds__(256) k1_partial_ch1(
        const float* __restrict__ in,
        const float* __restrict__ alpha_p,
        const float* __restrict__ w,
        const float* __restrict__ bi,
        float* __restrict__ res) {
    int id = blockIdx.x * blockDim.x + threadIdx.x;
    if (id >= Bv * NCH * Fv) return;
    int f  = id % Fv;
    int bc = id / Fv;
    int ch = bc % NCH;
    int b  = bc / NCH;

    float alpha = sigmoidf(alpha_p[f]);
    float w1 = w[Fv + f];
    float b1 = bi[Fv + f];

    size_t base0 = ((size_t)(b * Cv + 0) * Tv + (size_t)ch * Lc) * Fv + f;
    size_t base1 = ((size_t)(b * Cv + 1) * Tv + (size_t)ch * Lc) * Fv + f;
    const float2* x0 = (const float2*)in + base0;
    const float2* x1 = (const float2*)in + base1;
    float2* r1 = (float2*)res + base1;

    float s = 0.0f;
#pragma unroll 5
    for (int t = 0; t < Lc; ++t) {
        // channel-0 partial scan (keep ch0 in L2 for K3: default load policy)
        float2 v0 = x0[(size_t)t * Fv];
        float m = fmaf(v0.x, v0.x, v0.y * v0.y);
        s = fmaf(alpha, m - s, s);          // s = s*(1-a) + m*a

        // channel-1 elementwise (streaming: evict-first both ways)
        float2 v1 = __ldcs(&x1[(size_t)t * Fv]);
        float mag = sqrtf(fmaf(v1.x, v1.x, v1.y * v1.y));
        float inv = w1 / (mag + 1e-8f);
        float2 o;
        o.x = fmaf(v1.x, inv, b1);
        o.y = fmaf(v1.y, inv, b1);
        __stcs(&r1[(size_t)t * Fv], o);
    }
    g_e[ch * BF + b * Fv + f] = s;
}

// K2: sequential combine over NCH chunks per chain: carry[k] = state before chunk k.
__global__ void k2_combine(const float* __restrict__ s1,
                           const float* __restrict__ alpha_p) {
    int id = blockIdx.x * blockDim.x + threadIdx.x;  // id = b*Fv + f
    if (id >= BF) return;
    int f = id % Fv;
    float alpha = sigmoidf(alpha_p[f]);
    float aL = powf(1.0f - alpha, (float)Lc);
    float s = s1[id];                                // s_1[b,0,f,0]
#pragma unroll
    for (int k = 0; k < NCH; ++k) {
        g_carry[k * BF + id] = s;
        s = fmaf(aL, s, g_e[k * BF + id]);           // state after chunk k
    }
}

// K3: re-scan each chunk with correct carry-in; emit smooth (sqrt) + res channel 0.
__global__ void __launch_bounds__(256) k3_final(
        const float* __restrict__ in,
        const float* __restrict__ alpha_p,
        const float* __restrict__ w,
        const float* __restrict__ bi,
        float* __restrict__ res,
        float* __restrict__ sfin,
        float* __restrict__ smooth) {
    int id = blockIdx.x * blockDim.x + threadIdx.x;
    if (id >= Bv * NCH * Fv) return;
    int f  = id % Fv;
    int bc = id / Fv;
    int ch = bc % NCH;
    int b  = bc / NCH;

    float alpha = sigmoidf(alpha_p[f]);
    float w0 = w[f];
    float b0 = bi[f];
    float s = g_carry[ch * BF + b * Fv + f];

    size_t base = ((size_t)(b * Cv + 0) * Tv + (size_t)ch * Lc) * Fv + f;
    const float2* x = (const float2*)in + base;
    float2* r = (float2*)res + base;
    float* sm = smooth ? smooth + ((size_t)b * Tv + (size_t)ch * Lc) * Fv + f : (float*)0;

#pragma unroll 5
    for (int t = 0; t < Lc; ++t) {
        float2 v = x[(size_t)t * Fv];           // hopefully L2-resident from K1
        float m = fmaf(v.x, v.x, v.y * v.y);
        s = fmaf(alpha, m - s, s);
        float sd = sqrtf(s);
        float inv = w0 / (sd + 1e-8f);
        float2 o;
        o.x = fmaf(v.x, inv, b0);
        o.y = fmaf(v.y, inv, b0);
        __stcs(&r[(size_t)t * Fv], o);
        if (sm) __stcs(&sm[(size_t)t * Fv], sd);
    }
    if (ch == NCH - 1 && sfin) sfin[b * Fv + f] = s;   // s_final == last smooth state
}

extern "C" void kernel_launch(void* const* d_in, const int* in_sizes, int n_in,
                              void* d_out, int out_size) {
    const float* in  = (const float*)d_in[0];   // [B,C,T,F,2]
    const float* s1  = (const float*)d_in[1];   // [B,1,F,1]
    const float* w   = (const float*)d_in[2];   // [1,C,1,F,1]
    const float* bi  = (const float*)d_in[3];   // [1,C,1,F,1]
    const float* ap  = (const float*)d_in[4];   // [1,1,F,1]

    float* out = (float*)d_out;
    const long long RESN = (long long)Bv * Cv * Tv * Fv * 2;  // 32,896,000
    const long long SFN  = (long long)BF;                     // 4,112
    const long long SMN  = (long long)Bv * Tv * Fv;           // 8,224,000

    float* res    = out;
    float* sfin   = (float*)0;
    float* smooth = (float*)0;
    long long osz = (long long)out_size;
    if (osz >= RESN + SFN + SMN) {            // (res, s_final, smooth_data) concatenated
        sfin   = out + RESN;
        smooth = out + RESN + SFN;
    } else if (osz >= RESN + SMN) {           // (res, smooth_data)
        smooth = out + RESN;
    }

    const int BLK = 256;
    int n1 = Bv * NCH * Fv;                   // 164,480
    k1_partial_ch1<<<(n1 + BLK - 1) / BLK, BLK>>>(in, ap, w, bi, res);
    k2_combine<<<(BF + BLK - 1) / BLK, BLK>>>(s1, ap);
    k3_final  <<<(n1 + BLK - 1) / BLK, BLK>>>(in, ap, w, bi, res, sfin, smooth);
}

// round 3
// speedup vs baseline: 1.2244x; 1.0872x over previous
#include <cuda_runtime.h>

// Problem constants
#define Bv   16
#define Cv   2
#define Tv   2000
#define Fv   257
#define NCH  50          // number of time chunks
#define Lc   40          // chunk length (NCH*Lc == Tv)
#define BF   (Bv*Fv)     // 4112 independent scan chains

// Scratch (no cudaMalloc allowed): chunk-end partials and carry-ins.
__device__ float g_e[NCH * BF];
__device__ float g_carry[NCH * BF];

__device__ __forceinline__ float sigmoidf(float x) {
    return 1.0f / (1.0f + expf(-x));
}
__device__ __forceinline__ float sqrt_approx(float x) {
    float r;
    asm("sqrt.approx.f32 %0, %1;" : "=f"(r) : "f"(x));
    return r;
}

// K1 (fused): chunk-local EMA partial scan on channel 0 (zero init state,
// record chunk-end value), PLUS the independent channel-1 elementwise
// normalization for the same (b, t, f) range.
__global__ void __launch_bounds__(128) k1_partial_ch1(
        const float* __restrict__ in,
        const float* __restrict__ alpha_p,
        const float* __restrict__ w,
        const float* __restrict__ bi,
        float* __restrict__ res) {
    int id = blockIdx.x * blockDim.x + threadIdx.x;
    if (id >= Bv * NCH * Fv) return;
    int f  = id % Fv;
    int bc = id / Fv;
    int ch = bc % NCH;
    int b  = bc / NCH;

    float alpha = sigmoidf(alpha_p[f]);
    float w1 = w[Fv + f];
    float b1 = bi[Fv + f];

    size_t base0 = ((size_t)(b * Cv + 0) * Tv + (size_t)ch * Lc) * Fv + f;
    size_t base1 = ((size_t)(b * Cv + 1) * Tv + (size_t)ch * Lc) * Fv + f;
    const float2* x0 = (const float2*)in + base0;
    const float2* x1 = (const float2*)in + base1;
    float2* r1 = (float2*)res + base1;

    float s = 0.0f;
#pragma unroll 8
    for (int t = 0; t < Lc; ++t) {
        // channel-0 partial scan (default policy: keep ch0 in L2 for K3)
        float2 v0 = x0[(size_t)t * Fv];
        float m = fmaf(v0.x, v0.x, v0.y * v0.y);
        s = fmaf(alpha, m - s, s);          // s = s*(1-a) + m*a

        // channel-1 elementwise (streaming: evict-first both ways)
        float2 v1 = __ldcs(&x1[(size_t)t * Fv]);
        float mag = sqrt_approx(fmaf(v1.x, v1.x, v1.y * v1.y));
        float inv = __fdividef(w1, mag + 1e-8f);
        float2 o;
        o.x = fmaf(v1.x, inv, b1);
        o.y = fmaf(v1.y, inv, b1);
        __stcs(&r1[(size_t)t * Fv], o);
    }
    g_e[ch * BF + b * Fv + f] = s;
}

// K2: sequential combine over NCH chunks per chain: carry[k] = state before chunk k.
__global__ void k2_combine(const float* __restrict__ s1,
                           const float* __restrict__ alpha_p) {
    int id = blockIdx.x * blockDim.x + threadIdx.x;  // id = b*Fv + f
    if (id >= BF) return;
    int f = id % Fv;
    float alpha = sigmoidf(alpha_p[f]);
    float aL = powf(1.0f - alpha, (float)Lc);
    float s = s1[id];                                // s_1[b,0,f,0]
#pragma unroll
    for (int k = 0; k < NCH; ++k) {
        g_carry[k * BF + id] = s;
        s = fmaf(aL, s, g_e[k * BF + id]);           // state after chunk k
    }
}

// K3: re-scan each chunk with correct carry-in; emit smooth (sqrt) + res channel 0.
__global__ void __launch_bounds__(128) k3_final(
        const float* __restrict__ in,
        const float* __restrict__ alpha_p,
        const float* __restrict__ w,
        const float* __restrict__ bi,
        float* __restrict__ res,
        float* __restrict__ sfin,
        float* __restrict__ smooth) {
    int id = blockIdx.x * blockDim.x + threadIdx.x;
    if (id >= Bv * NCH * Fv) return;
    int f  = id % Fv;
    int bc = id / Fv;
    int ch = bc % NCH;
    int b  = bc / NCH;

    float alpha = sigmoidf(alpha_p[f]);
    float w0 = w[f];
    float b0 = bi[f];
    float s = g_carry[ch * BF + b * Fv + f];

    size_t base = ((size_t)(b * Cv + 0) * Tv + (size_t)ch * Lc) * Fv + f;
    const float2* x = (const float2*)in + base;
    float2* r = (float2*)res + base;
    float* sm = smooth ? smooth + ((size_t)b * Tv + (size_t)ch * Lc) * Fv + f : (float*)0;

#pragma unroll 8
    for (int t = 0; t < Lc; ++t) {
        float2 v = __ldcs(&x[(size_t)t * Fv]);   // L2-resident from K1 (last use)
        float m = fmaf(v.x, v.x, v.y * v.y);
        s = fmaf(alpha, m - s, s);
        float sd = sqrt_approx(s);
        float inv = __fdividef(w0, sd + 1e-8f);
        float2 o;
        o.x = fmaf(v.x, inv, b0);
        o.y = fmaf(v.y, inv, b0);
        __stcs(&r[(size_t)t * Fv], o);
        if (sm) __stcs(&sm[(size_t)t * Fv], sd);
    }
    if (ch == NCH - 1 && sfin) sfin[b * Fv + f] = s;   // s_final == last smooth state
}

extern "C" void kernel_launch(void* const* d_in, const int* in_sizes, int n_in,
                              void* d_out, int out_size) {
    const float* in  = (const float*)d_in[0];   // [B,C,T,F,2]
    const float* s1  = (const float*)d_in[1];   // [B,1,F,1]
    const float* w   = (const float*)d_in[2];   // [1,C,1,F,1]
    const float* bi  = (const float*)d_in[3];   // [1,C,1,F,1]
    const float* ap  = (const float*)d_in[4];   // [1,1,F,1]

    float* out = (float*)d_out;
    const long long RESN = (long long)Bv * Cv * Tv * Fv * 2;  // 32,896,000
    const long long SFN  = (long long)BF;                     // 4,112
    const long long SMN  = (long long)Bv * Tv * Fv;           // 8,224,000

    float* res    = out;
    float* sfin   = (float*)0;
    float* smooth = (float*)0;
    long long osz = (long long)out_size;
    if (osz >= RESN + SFN + SMN) {            // (res, s_final, smooth_data) concatenated
        sfin   = out + RESN;
        smooth = out + RESN + SFN;
    } else if (osz >= RESN + SMN) {           // (res, smooth_data)
        smooth = out + RESN;
    }

    const int BLK = 128;
    int n1 = Bv * NCH * Fv;                   // 205,600
    k1_partial_ch1<<<(n1 + BLK - 1) / BLK, BLK>>>(in, ap, w, bi, res);
    k2_combine<<<(BF + 255) / 256, 256>>>(s1, ap);
    k3_final  <<<(n1 + BLK - 1) / BLK, BLK>>>(in, ap, w, bi, res, sfin, smooth);
}